// round 2
// baseline (speedup 1.0000x reference)
#include <cuda_runtime.h>

#define CHN 128
#define KS  5
#define HH  128
#define WW  128
#define TH  4          // rows per block
#define CSPLIT 2
#define CPB (CHN/CSPLIT)   // 64 channels per block

__global__ __launch_bounds__(256, 2)
void dwconv_ksa_kernel(const float* __restrict__ x,
                       const float* __restrict__ ksa,
                       const float* __restrict__ w,
                       const float* __restrict__ b,
                       float* __restrict__ out)
{
    // grid: (H/TH, N, CSPLIT); block: (64, TH)
    const int tx = threadIdx.x;           // 0..63  -> w-pair index
    const int ty = threadIdx.y;           // 0..TH-1
    const int h0 = blockIdx.x * TH;
    const int n  = blockIdx.y;
    const int c0 = blockIdx.z * CPB;

    __shared__ float ws[CPB * 25];
    __shared__ float bs[CPB];

    const int tid = ty * 64 + tx;
    // w is (CH, 5, 5) contiguous -> flat c*25 + t
    for (int i = tid; i < CPB * 25; i += 256) ws[i] = w[c0 * 25 + i];
    if (tid < CPB) bs[tid] = b[c0 + tid];

    const int h  = h0 + ty;
    const int w0 = tx * 2;

    // ---- load ksa for this pixel pair into registers, fold boundary masks ----
    float2 kk[25];
    const float* ksabase = ksa + ((size_t)(n * 25) * HH + h) * WW + w0;
    #pragma unroll
    for (int t = 0; t < 25; t++) {
        float2 v = *(const float2*)(ksabase + (size_t)t * HH * WW);
        const int i = t / 5, j = t % 5;
        const int r  = h + i - 2;
        const bool rok = (r >= 0) && (r < HH);
        const int cA = w0 + j - 2;       // column for pixel w0
        const int cB = cA + 1;           // column for pixel w0+1
        v.x = (rok && cA >= 0 && cA < WW) ? v.x : 0.0f;
        v.y = (rok && cB >= 0 && cB < WW) ? v.y : 0.0f;
        kk[t] = v;
    }

    // clamped row offsets (garbage rows are masked via kk==0)
    int rowoff[5];
    #pragma unroll
    for (int i = 0; i < 5; i++) {
        int r = h + i - 2;
        r = r < 0 ? 0 : (r > HH - 1 ? HH - 1 : r);
        rowoff[i] = r * WW;
    }
    // clamped column bases for the three float2 loads per row (all even -> 8B aligned)
    const int e0 = (w0 - 2 < 0) ? 0 : (w0 - 2);
    const int e2 = (w0 + 2 > WW - 2) ? (WW - 2) : (w0 + 2);

    __syncthreads();

    const float* xn   = x   + (size_t)(n * CHN + c0) * HH * WW;
    float*       outp = out + ((size_t)(n * CHN + c0) * HH + h) * WW + w0;

    for (int cl = 0; cl < CPB; ++cl) {
        const float* xc = xn + (size_t)cl * HH * WW;
        const float* wc = ws + cl * 25;
        float acc0 = 0.0f, acc1 = 0.0f;

        #pragma unroll
        for (int i = 0; i < 5; i++) {
            const float* row = xc + rowoff[i];
            const float2 A = *(const float2*)(row + e0);   // x[w0-2], x[w0-1]
            const float2 B = *(const float2*)(row + w0);   // x[w0  ], x[w0+1]
            const float2 C = *(const float2*)(row + e2);   // x[w0+2], x[w0+3]
            const float w0v = wc[i*5+0];
            const float w1v = wc[i*5+1];
            const float w2v = wc[i*5+2];
            const float w3v = wc[i*5+3];
            const float w4v = wc[i*5+4];
            // out0 = pixel w0, out1 = pixel w0+1
            acc0 = fmaf(kk[i*5+0].x * w0v, A.x, acc0);
            acc1 = fmaf(kk[i*5+0].y * w0v, A.y, acc1);
            acc0 = fmaf(kk[i*5+1].x * w1v, A.y, acc0);
            acc1 = fmaf(kk[i*5+1].y * w1v, B.x, acc1);
            acc0 = fmaf(kk[i*5+2].x * w2v, B.x, acc0);
            acc1 = fmaf(kk[i*5+2].y * w2v, B.y, acc1);
            acc0 = fmaf(kk[i*5+3].x * w3v, B.y, acc0);
            acc1 = fmaf(kk[i*5+3].y * w3v, C.x, acc1);
            acc0 = fmaf(kk[i*5+4].x * w4v, C.x, acc0);
            acc1 = fmaf(kk[i*5+4].y * w4v, C.y, acc1);
        }

        const float bb = bs[cl];
        float2 o;
        o.x = acc0 + bb;
        o.y = acc1 + bb;
        *(float2*)(outp + (size_t)cl * HH * WW) = o;
    }
}

extern "C" void kernel_launch(void* const* d_in, const int* in_sizes, int n_in,
                              void* d_out, int out_size)
{
    const float* x   = (const float*)d_in[0];
    const float* ksa = (const float*)d_in[1];
    const float* w   = (const float*)d_in[2];
    const float* b   = (const float*)d_in[3];
    float* out = (float*)d_out;

    const int n_batch = in_sizes[0] / (CHN * HH * WW);   // = 4

    dim3 block(64, TH);
    dim3 grid(HH / TH, n_batch, CSPLIT);
    dwconv_ksa_kernel<<<grid, block>>>(x, ksa, w, b, out);
}